// round 13
// baseline (speedup 1.0000x reference)
#include <cuda_runtime.h>

// PoseODE: y' = MLP(y), y0 = 0, batch-invariant -> single 768-vector trajectory.
// 512 sequential matvec stages across 64 CTAs (12 columns each). Cross-CTA
// exchange: SINGLE-WRITER 64B packet per CTA per round, four self-validating
// 16B chunks {tag,v,v,v}. R13: layer-2 dot fused with packet arrival -- every
// warp polls all 64 h-packets (lane l owns packets 2l,2l+1 = rows 24l..24l+23,
// whose W2 block lives in that lane's registers); no hsm scatter, no barrier,
// no SMEM re-read for layer 2. k-exchange keeps the R9 one-poller path.
// Monotonic tags -> no init, replay-safe.

#define F      768
#define G      64    // CTAs
#define NC     12    // columns per CTA
#define WP     6     // warps per CTA; warp w owns columns bid*12 + 2w, 2w+1
#define T      192
#define NSTEP  64

// packet row = 4 x uint4 = 64B: chunk c = {tag, v(3c), v(3c+1), v(3c+2)}
__device__ __align__(128) uint4 g_x[2][G][4] = {};
__device__ __align__(128) uint2 g_s[2][256]  = {};   // regressor rounds

static __device__ __forceinline__ uint4 ldcg_v4(const void* p) {
    uint4 r;
    asm volatile("ld.global.cg.v4.u32 {%0,%1,%2,%3},[%4];"
                 : "=r"(r.x), "=r"(r.y), "=r"(r.z), "=r"(r.w) : "l"(p));
    return r;
}
static __device__ __forceinline__ void stcg_v4(uint4* p, unsigned a, unsigned b,
                                               unsigned c, unsigned d) {
    asm volatile("st.global.cg.v4.u32 [%0],{%1,%2,%3,%4};"
                 :: "l"(p), "r"(a), "r"(b), "r"(c), "r"(d) : "memory");
}
static __device__ __forceinline__ void pub8(uint2* s, float v, unsigned tag) {
    asm volatile("st.global.cg.v2.u32 [%0],{%1,%2};"
                 :: "l"(s), "r"(__float_as_uint(v)), "r"(tag) : "memory");
}
static __device__ __forceinline__ float wait8(const uint2* s, unsigned tag) {
    unsigned v, t;
    do {
        asm volatile("ld.global.cg.v2.u32 {%0,%1},[%2];" : "=r"(v), "=r"(t) : "l"(s));
    } while (t != tag);
    return __uint_as_float(v);
}

static __device__ __forceinline__ float warp_sum(float a) {
#pragma unroll
    for (int o = 16; o; o >>= 1) a += __shfl_xor_sync(0xffffffffu, a, o);
    return a;
}

// Simple dependent poll of one 64B packet (R9-proven). Returns 12 values.
static __device__ __forceinline__ void wait_packet(const uint4* p, unsigned tag, float* o) {
    uint4 a, b, c, d;
    do {
        a = ldcg_v4(p);
        b = ldcg_v4(p + 1);
        c = ldcg_v4(p + 2);
        d = ldcg_v4(p + 3);
    } while ((a.x ^ tag) | (b.x ^ tag) | (c.x ^ tag) | (d.x ^ tag));
    o[0]=__uint_as_float(a.y); o[1] =__uint_as_float(a.z); o[2] =__uint_as_float(a.w);
    o[3]=__uint_as_float(b.y); o[4] =__uint_as_float(b.z); o[5] =__uint_as_float(b.w);
    o[6]=__uint_as_float(c.y); o[7] =__uint_as_float(c.z); o[8] =__uint_as_float(c.w);
    o[9]=__uint_as_float(d.y); o[10]=__uint_as_float(d.z); o[11]=__uint_as_float(d.w);
}

// Poll TWO consecutive packets (128B); returns 24 values (rows 24l..24l+23).
static __device__ __forceinline__ void wait_2packets(const uint4* p, unsigned tag, float* o) {
    uint4 a, b, c, d, e, f, g, h;
    do {
        a = ldcg_v4(p);     b = ldcg_v4(p + 1);
        c = ldcg_v4(p + 2); d = ldcg_v4(p + 3);
        e = ldcg_v4(p + 4); f = ldcg_v4(p + 5);
        g = ldcg_v4(p + 6); h = ldcg_v4(p + 7);
    } while ((a.x ^ tag) | (b.x ^ tag) | (c.x ^ tag) | (d.x ^ tag) |
             (e.x ^ tag) | (f.x ^ tag) | (g.x ^ tag) | (h.x ^ tag));
    o[0] =__uint_as_float(a.y); o[1] =__uint_as_float(a.z); o[2] =__uint_as_float(a.w);
    o[3] =__uint_as_float(b.y); o[4] =__uint_as_float(b.z); o[5] =__uint_as_float(b.w);
    o[6] =__uint_as_float(c.y); o[7] =__uint_as_float(c.z); o[8] =__uint_as_float(c.w);
    o[9] =__uint_as_float(d.y); o[10]=__uint_as_float(d.z); o[11]=__uint_as_float(d.w);
    o[12]=__uint_as_float(e.y); o[13]=__uint_as_float(e.z); o[14]=__uint_as_float(e.w);
    o[15]=__uint_as_float(f.y); o[16]=__uint_as_float(f.z); o[17]=__uint_as_float(f.w);
    o[18]=__uint_as_float(g.y); o[19]=__uint_as_float(g.z); o[20]=__uint_as_float(g.w);
    o[21]=__uint_as_float(h.y); o[22]=__uint_as_float(h.z); o[23]=__uint_as_float(h.w);
}

static __device__ __forceinline__ float lrelu(float x) { return x > 0.0f ? x : 0.1f * x; }

// Layer-1 dot from SMEM vector, two columns per warp; fused reduction returns
// colA sum on lanes 0-15, colB sum on lanes 16-31 (5 shuffles).
static __device__ __forceinline__ float dot2_smem(const float4* __restrict__ src4,
                                                  const float4* wa, const float4* wb,
                                                  int lane, int half) {
    float a0=0.f, a1=0.f, b0=0.f, b1=0.f;
#pragma unroll
    for (int k = 0; k < 6; k += 2) {
        float4 v0 = src4[k * 32 + lane];
        float4 v1 = src4[(k + 1) * 32 + lane];
        a0 = fmaf(v0.x, wa[k].x, a0);   b0 = fmaf(v0.x, wb[k].x, b0);
        a0 = fmaf(v0.y, wa[k].y, a0);   b0 = fmaf(v0.y, wb[k].y, b0);
        a0 = fmaf(v0.z, wa[k].z, a0);   b0 = fmaf(v0.z, wb[k].z, b0);
        a0 = fmaf(v0.w, wa[k].w, a0);   b0 = fmaf(v0.w, wb[k].w, b0);
        a1 = fmaf(v1.x, wa[k+1].x, a1); b1 = fmaf(v1.x, wb[k+1].x, b1);
        a1 = fmaf(v1.y, wa[k+1].y, a1); b1 = fmaf(v1.y, wb[k+1].y, b1);
        a1 = fmaf(v1.z, wa[k+1].z, a1); b1 = fmaf(v1.z, wb[k+1].z, b1);
        a1 = fmaf(v1.w, wa[k+1].w, a1); b1 = fmaf(v1.w, wb[k+1].w, b1);
    }
    float a = a0 + a1, b = b0 + b1;
    float keep = half ? b : a;
    float give = half ? a : b;
    float x = keep + __shfl_xor_sync(0xffffffffu, give, 16);
#pragma unroll
    for (int o = 8; o; o >>= 1) x += __shfl_xor_sync(0xffffffffu, x, o);
    return x;
}

// Layer-2 dot from the 24 register-resident h values (rows 24l..24l+23),
// weights w2a/w2b = this lane's 24-row block for cols 2w / 2w+1.
static __device__ __forceinline__ float dot2_reg(const float* hv,
                                                 const float4* wa, const float4* wb,
                                                 int half) {
    float a0=0.f, a1=0.f, b0=0.f, b1=0.f;
#pragma unroll
    for (int q = 0; q < 6; q += 2) {
        a0 = fmaf(hv[4*q+0], wa[q].x, a0);   b0 = fmaf(hv[4*q+0], wb[q].x, b0);
        a0 = fmaf(hv[4*q+1], wa[q].y, a0);   b0 = fmaf(hv[4*q+1], wb[q].y, b0);
        a0 = fmaf(hv[4*q+2], wa[q].z, a0);   b0 = fmaf(hv[4*q+2], wb[q].z, b0);
        a0 = fmaf(hv[4*q+3], wa[q].w, a0);   b0 = fmaf(hv[4*q+3], wb[q].w, b0);
        a1 = fmaf(hv[4*q+4], wa[q+1].x, a1); b1 = fmaf(hv[4*q+4], wb[q+1].x, b1);
        a1 = fmaf(hv[4*q+5], wa[q+1].y, a1); b1 = fmaf(hv[4*q+5], wb[q+1].y, b1);
        a1 = fmaf(hv[4*q+6], wa[q+1].z, a1); b1 = fmaf(hv[4*q+6], wb[q+1].z, b1);
        a1 = fmaf(hv[4*q+7], wa[q+1].w, a1); b1 = fmaf(hv[4*q+7], wb[q+1].w, b1);
    }
    float a = a0 + a1, b = b0 + b1;
    float keep = half ? b : a;
    float give = half ? a : b;
    float x = keep + __shfl_xor_sync(0xffffffffu, give, 16);
#pragma unroll
    for (int o = 8; o; o >>= 1) x += __shfl_xor_sync(0xffffffffu, x, o);
    return x;
}

// Block-wide dot of SMEM vector src[0..L) with column `col` of wmat[L][outF].
__device__ __forceinline__ float block_dot(const float* src, int L,
                                           const float* wmat, int outF, int col,
                                           const float* bias, volatile float* red) {
    int tid = threadIdx.x, warp = tid >> 5, lane = tid & 31;
    float p = 0.0f;
    for (int i = tid; i < L; i += T) p = fmaf(src[i], __ldg(&wmat[i * outF + col]), p);
    p = warp_sum(p);
    if (lane == 0) red[warp] = p;
    __syncthreads();
    float s = 0.0f;
    if (tid == 0) {
        for (int w = 0; w < WP; w++) s += red[w];
        s += __ldg(&bias[col]);
    }
    __syncthreads();
    return s;
}

// tid0: read 12 packed values from pack4, publish as 4 self-validating chunks.
static __device__ __forceinline__ void publish12(const float4* pack4, unsigned tag,
                                                 uint4* base) {
    float4 p0 = pack4[0], p1 = pack4[1], p2 = pack4[2];
    stcg_v4(base+0, tag, __float_as_uint(p0.x), __float_as_uint(p0.y), __float_as_uint(p0.z));
    stcg_v4(base+1, tag, __float_as_uint(p0.w), __float_as_uint(p1.x), __float_as_uint(p1.y));
    stcg_v4(base+2, tag, __float_as_uint(p1.z), __float_as_uint(p1.w), __float_as_uint(p2.x));
    stcg_v4(base+3, tag, __float_as_uint(p2.y), __float_as_uint(p2.z), __float_as_uint(p2.w));
}

__global__ __launch_bounds__(T, 1) void pose_ode_kernel(
    const float* __restrict__ ts,
    const float* __restrict__ w1, const float* __restrict__ b1,
    const float* __restrict__ w2, const float* __restrict__ b2,
    const float* __restrict__ rw1, const float* __restrict__ rb1,
    const float* __restrict__ rw2, const float* __restrict__ rb2,
    const float* __restrict__ rw3, const float* __restrict__ rb3,
    const float* __restrict__ rw4, const float* __restrict__ rb4,
    float* __restrict__ out, int out_n)
{
    __shared__ float  wstage[NC * F];    // 36 KB one-time staging; regressor scratch
    __shared__ float4 vsm4[F / 4];       // stage input vector / final yT
    __shared__ float4 hsm4[F / 4];       // regressor scratch only
    __shared__ float4 pack4[3];          // 12 packed outputs
    __shared__ float  red[8];
    __shared__ float  pose_s[8];
    __shared__ float  dts[NSTEP];

    float* vsm = (float*)vsm4;
    float* hsm = (float*)hsm4;
    float* pack_s = (float*)pack4;

    const int tid  = threadIdx.x;
    const int warp = tid >> 5;
    const int lane = tid & 31;
    const int half = (lane >> 4) & 1;    // lane0 -> col 2w, lane16 -> col 2w+1
    const int bid  = blockIdx.x;
    const int c0   = bid * NC;

    if (tid < NSTEP) dts[tid] = __ldg(&ts[tid + 1]) - __ldg(&ts[tid]);

    // ---- stage W1 columns into SMEM (coalesced), layer-1 layout to regs ----
    float4 w1a[6], w1b[6], w2a[6], w2b[6];
    for (int idx = tid; idx < NC * F; idx += T) {
        int i = idx / NC, r = idx - i * NC;
        wstage[r * F + i] = w1[i * F + c0 + r];
    }
    __syncthreads();
#pragma unroll
    for (int k = 0; k < 6; k++) {
        w1a[k] = ((const float4*)(wstage + (2 * warp)     * F))[k * 32 + lane];
        w1b[k] = ((const float4*)(wstage + (2 * warp + 1) * F))[k * 32 + lane];
    }
    __syncthreads();
    // ---- stage W2; layer-2 (arrival-fused) layout: lane l owns rows 24l..24l+23
    for (int idx = tid; idx < NC * F; idx += T) {
        int i = idx / NC, r = idx - i * NC;
        wstage[r * F + i] = w2[i * F + c0 + r];
    }
    __syncthreads();
#pragma unroll
    for (int q = 0; q < 6; q++) {
        w2a[q] = ((const float4*)(wstage + (2 * warp)     * F))[lane * 6 + q];
        w2b[q] = ((const float4*)(wstage + (2 * warp + 1) * F))[lane * 6 + q];
    }

    // per-lane bias for this lane's writer column (lane0: 2w, lane16: 2w+1)
    const float b1c = __ldg(&b1[c0 + 2 * warp + half]);
    const float b2c = __ldg(&b2[c0 + 2 * warp + half]);

    // ---- initial state: y0 = 0 ----
    if (tid < F / 4) vsm4[tid] = make_float4(0.f, 0.f, 0.f, 0.f);
    __syncthreads();

    // Poller thread t (<64) owns state elements [12t, 12t+12) == its k-packet.
    float yr[12], ynr[12], k1r[12], k2r[12];
#pragma unroll
    for (int q = 0; q < 12; q++) yr[q] = 0.f;
    unsigned rnd = 0;

#pragma unroll 1
    for (int s = 0; s < NSTEP; s++) {
        const float dt  = dts[s];
        const float dt3 = dt * (1.0f / 3.0f);

#pragma unroll 1
        for (int e = 0; e < 4; e++) {
            // ---- layer 1: h = tanh(v @ W1 + b1) from SMEM vector ----
            float acc = dot2_smem(vsm4, w1a, w1b, lane, half);
            float hvv = tanhf(acc + b1c);
            if (lane == 0 || lane == 16) pack_s[2 * warp + half] = hvv;
            __syncthreads();                    // pack_s(h) complete
            unsigned th = ++rnd;
            if (tid == 0) publish12(pack4, th, g_x[th & 1][bid]);

            // ---- layer 2, arrival-fused: every warp polls all 64 packets,
            //      lane l consumes packets 2l,2l+1 (its 24-row W2 block).
            //      No barrier: pack_s(k) writes can't precede tid0's publish
            //      (consuming h from L2 implies the publish happened).
            float hv[24];
            wait_2packets(g_x[th & 1][2 * lane], th, hv);
            float acc2 = dot2_reg(hv, w2a, w2b, half);
            float kvv = acc2 + b2c;
            if (lane == 0 || lane == 16) pack_s[2 * warp + half] = kvv;
            __syncthreads();                    // pack_s(k) complete
            unsigned tk = ++rnd;
            if (tid == 0) publish12(pack4, tk, g_x[tk & 1][bid]);
            if (tid < G) {
                float kv[12], vv[12];
                wait_packet(g_x[tk & 1][tid], tk, kv);
                if (e == 0) {
#pragma unroll
                    for (int q = 0; q < 12; q++) {
                        k1r[q] = kv[q];
                        ynr[q] = fmaf(dt * 0.125f, kv[q], yr[q]);
                        vv[q]  = fmaf(dt3, kv[q], yr[q]);
                    }
                } else if (e == 1) {
#pragma unroll
                    for (int q = 0; q < 12; q++) {
                        k2r[q] = kv[q];
                        ynr[q] = fmaf(dt * 0.375f, kv[q], ynr[q]);
                        vv[q]  = yr[q] + dt * kv[q] - dt3 * k1r[q];
                    }
                } else if (e == 2) {
#pragma unroll
                    for (int q = 0; q < 12; q++) {
                        ynr[q] = fmaf(dt * 0.375f, kv[q], ynr[q]);
                        vv[q]  = yr[q] + dt * (k1r[q] - k2r[q] + kv[q]);
                    }
                } else {
#pragma unroll
                    for (int q = 0; q < 12; q++) {
                        yr[q] = fmaf(dt * 0.125f, kv[q], ynr[q]);
                        vv[q] = yr[q];
                    }
                }
                float4* v = (float4*)(vsm + tid * 12);
                v[0] = make_float4(vv[0], vv[1], vv[2],  vv[3]);
                v[1] = make_float4(vv[4], vv[5], vv[6],  vv[7]);
                v[2] = make_float4(vv[8], vv[9], vv[10], vv[11]);
            }
            __syncthreads();                    // vsm complete
        }
    }
    // vsm now holds yT (not modified below).

    // ---- regressor 768->128->256->128->6 via tagged 8B rounds ----
    float* scratch = wstage;   // weight staging no longer needed
    {
        float o1a = block_dot(vsm, 768, rw1, 128, bid,      rb1, red);
        float o1b = block_dot(vsm, 768, rw1, 128, bid + 64, rb1, red);
        unsigned tr = ++rnd; uint2* b = g_s[tr & 1];
        if (tid == 0) {
            pub8(&b[bid],      lrelu(o1a), tr);
            pub8(&b[bid + 64], lrelu(o1b), tr);
        }
        if (tid < 128) hsm[tid] = wait8(&b[tid], tr);
        __syncthreads();

        float o2[4];
#pragma unroll
        for (int m = 0; m < 4; m++)
            o2[m] = block_dot(hsm, 128, rw2, 256, bid + m * 64, rb2, red);
        tr = ++rnd; b = g_s[tr & 1];
        if (tid == 0)
#pragma unroll
            for (int m = 0; m < 4; m++) pub8(&b[bid + m * 64], lrelu(o2[m]), tr);
        for (int i = tid; i < 256; i += T) scratch[i] = wait8(&b[i], tr);
        __syncthreads();

        float o3a = block_dot(scratch, 256, rw3, 128, bid,      rb3, red);
        float o3b = block_dot(scratch, 256, rw3, 128, bid + 64, rb3, red);
        tr = ++rnd; b = g_s[tr & 1];
        if (tid == 0) {
            pub8(&b[bid],      lrelu(o3a), tr);
            pub8(&b[bid + 64], lrelu(o3b), tr);
        }
        __syncthreads();                 // hsm reads done above
        if (tid < 128) hsm[tid] = wait8(&b[tid], tr);
        __syncthreads();

        float o4 = block_dot(hsm, 128, rw4, 6, bid % 6, rb4, red);
        tr = ++rnd; b = g_s[tr & 1];
        if (tid == 0 && bid < 6) pub8(&b[bid], o4, tr);   // no activation
        if (tid < 6) pose_s[tid] = wait8(&b[tid], tr);
        __syncthreads();
    }

    // ---- outputs: [pose (256*6) | yT (256*768)] ----
    for (int idx = bid * T + tid; idx < out_n; idx += G * T) {
        out[idx] = (idx < 1536) ? pose_s[idx % 6] : vsm[(idx - 1536) % 768];
    }
}

extern "C" void kernel_launch(void* const* d_in, const int* in_sizes, int n_in,
                              void* d_out, int out_size) {
    // order: fv, fv_alter, fi, dec (unused), ts, ode_w1, ode_b1, ode_w2, ode_b2,
    // reg_w1, reg_b1, reg_w2, reg_b2, reg_w3, reg_b3, reg_w4, reg_b4
    const float* ts  = (const float*)d_in[4];
    const float* w1  = (const float*)d_in[5];
    const float* b1  = (const float*)d_in[6];
    const float* w2  = (const float*)d_in[7];
    const float* b2  = (const float*)d_in[8];
    const float* rw1 = (const float*)d_in[9];
    const float* rb1 = (const float*)d_in[10];
    const float* rw2 = (const float*)d_in[11];
    const float* rb2 = (const float*)d_in[12];
    const float* rw3 = (const float*)d_in[13];
    const float* rb3 = (const float*)d_in[14];
    const float* rw4 = (const float*)d_in[15];
    const float* rb4 = (const float*)d_in[16];

    pose_ode_kernel<<<G, T>>>(ts, w1, b1, w2, b2,
                              rw1, rb1, rw2, rb2, rw3, rb3, rw4, rb4,
                              (float*)d_out, out_size);
}

// round 14
// speedup vs baseline: 3.3699x; 3.3699x over previous
#include <cuda_runtime.h>

// PoseODE: y' = MLP(y), y0 = 0, batch-invariant -> single 768-vector trajectory.
// 512 sequential matvec stages across 64 CTAs (12 columns each). Cross-CTA
// exchange: SINGLE-WRITER 64B packet per CTA per round, four self-validating
// 16B chunks {tag,v,v,v}. Transport law (measured R5-R13): exactly ONE poller
// per packet, <=64B poll window, simple dependent poll -- wider/shared polling
// storms L2 (R6,R7,R11,R13 all regressed 2-6x). R14 = R9 structure + fused
// dual-column 5-shuffle reduction, uniform polling (no divergent branches).
// Monotonic tags -> no init, replay-safe.

#define F      768
#define G      64    // CTAs
#define NC     12    // columns per CTA
#define WP     6     // warps per CTA; warp w owns columns bid*12 + 2w, 2w+1
#define T      192
#define NSTEP  64

// packet row = 4 x uint4 = 64B: chunk c = {tag, v(3c), v(3c+1), v(3c+2)}
__device__ __align__(128) uint4 g_x[2][G][4] = {};
__device__ __align__(128) uint2 g_s[2][256]  = {};   // regressor rounds

static __device__ __forceinline__ uint4 ldcg_v4(const void* p) {
    uint4 r;
    asm volatile("ld.global.cg.v4.u32 {%0,%1,%2,%3},[%4];"
                 : "=r"(r.x), "=r"(r.y), "=r"(r.z), "=r"(r.w) : "l"(p));
    return r;
}
static __device__ __forceinline__ void stcg_v4(uint4* p, unsigned a, unsigned b,
                                               unsigned c, unsigned d) {
    asm volatile("st.global.cg.v4.u32 [%0],{%1,%2,%3,%4};"
                 :: "l"(p), "r"(a), "r"(b), "r"(c), "r"(d) : "memory");
}
static __device__ __forceinline__ void pub8(uint2* s, float v, unsigned tag) {
    asm volatile("st.global.cg.v2.u32 [%0],{%1,%2};"
                 :: "l"(s), "r"(__float_as_uint(v)), "r"(tag) : "memory");
}
static __device__ __forceinline__ float wait8(const uint2* s, unsigned tag) {
    unsigned v, t;
    do {
        asm volatile("ld.global.cg.v2.u32 {%0,%1},[%2];" : "=r"(v), "=r"(t) : "l"(s));
    } while (t != tag);
    return __uint_as_float(v);
}

static __device__ __forceinline__ float warp_sum(float a) {
#pragma unroll
    for (int o = 16; o; o >>= 1) a += __shfl_xor_sync(0xffffffffu, a, o);
    return a;
}

// Simple dependent poll of one 64B packet (R9-proven): 4 loads per iteration,
// self-paced at ~1 L2 round trip. Returns 12 values once all 4 tags match.
static __device__ __forceinline__ void wait_packet(const uint4* p, unsigned tag, float* o) {
    uint4 a, b, c, d;
    do {
        a = ldcg_v4(p);
        b = ldcg_v4(p + 1);
        c = ldcg_v4(p + 2);
        d = ldcg_v4(p + 3);
    } while ((a.x ^ tag) | (b.x ^ tag) | (c.x ^ tag) | (d.x ^ tag));
    o[0]=__uint_as_float(a.y); o[1] =__uint_as_float(a.z); o[2] =__uint_as_float(a.w);
    o[3]=__uint_as_float(b.y); o[4] =__uint_as_float(b.z); o[5] =__uint_as_float(b.w);
    o[6]=__uint_as_float(c.y); o[7] =__uint_as_float(c.z); o[8] =__uint_as_float(c.w);
    o[9]=__uint_as_float(d.y); o[10]=__uint_as_float(d.z); o[11]=__uint_as_float(d.w);
}

static __device__ __forceinline__ float lrelu(float x) { return x > 0.0f ? x : 0.1f * x; }

// Dot of the SMEM vector with TWO weight columns. Fused reduction: returns
// colA's sum on lanes 0-15 and colB's sum on lanes 16-31 (5 shuffles total).
static __device__ __forceinline__ float dot2(const float4* __restrict__ src4,
                                             const float4* wa, const float4* wb,
                                             int lane, int half) {
    float a0=0.f, a1=0.f, b0=0.f, b1=0.f;
#pragma unroll
    for (int k = 0; k < 6; k += 2) {
        float4 v0 = src4[k * 32 + lane];
        float4 v1 = src4[(k + 1) * 32 + lane];
        a0 = fmaf(v0.x, wa[k].x, a0);   b0 = fmaf(v0.x, wb[k].x, b0);
        a0 = fmaf(v0.y, wa[k].y, a0);   b0 = fmaf(v0.y, wb[k].y, b0);
        a0 = fmaf(v0.z, wa[k].z, a0);   b0 = fmaf(v0.z, wb[k].z, b0);
        a0 = fmaf(v0.w, wa[k].w, a0);   b0 = fmaf(v0.w, wb[k].w, b0);
        a1 = fmaf(v1.x, wa[k+1].x, a1); b1 = fmaf(v1.x, wb[k+1].x, b1);
        a1 = fmaf(v1.y, wa[k+1].y, a1); b1 = fmaf(v1.y, wb[k+1].y, b1);
        a1 = fmaf(v1.z, wa[k+1].z, a1); b1 = fmaf(v1.z, wb[k+1].z, b1);
        a1 = fmaf(v1.w, wa[k+1].w, a1); b1 = fmaf(v1.w, wb[k+1].w, b1);
    }
    float a = a0 + a1, b = b0 + b1;
    // keep own-column partial, receive other-column partial from partner half
    float keep = half ? b : a;
    float give = half ? a : b;
    float x = keep + __shfl_xor_sync(0xffffffffu, give, 16);
#pragma unroll
    for (int o = 8; o; o >>= 1) x += __shfl_xor_sync(0xffffffffu, x, o);
    return x;   // lanes 0-15: colA sum; lanes 16-31: colB sum
}

// Block-wide dot of SMEM vector src[0..L) with column `col` of wmat[L][outF].
__device__ __forceinline__ float block_dot(const float* src, int L,
                                           const float* wmat, int outF, int col,
                                           const float* bias, volatile float* red) {
    int tid = threadIdx.x, warp = tid >> 5, lane = tid & 31;
    float p = 0.0f;
    for (int i = tid; i < L; i += T) p = fmaf(src[i], __ldg(&wmat[i * outF + col]), p);
    p = warp_sum(p);
    if (lane == 0) red[warp] = p;
    __syncthreads();
    float s = 0.0f;
    if (tid == 0) {
        for (int w = 0; w < WP; w++) s += red[w];
        s += __ldg(&bias[col]);
    }
    __syncthreads();
    return s;
}

// tid0: read 12 packed values from pack4, publish as 4 self-validating chunks.
static __device__ __forceinline__ void publish12(const float4* pack4, unsigned tag,
                                                 uint4* base) {
    float4 p0 = pack4[0], p1 = pack4[1], p2 = pack4[2];
    stcg_v4(base+0, tag, __float_as_uint(p0.x), __float_as_uint(p0.y), __float_as_uint(p0.z));
    stcg_v4(base+1, tag, __float_as_uint(p0.w), __float_as_uint(p1.x), __float_as_uint(p1.y));
    stcg_v4(base+2, tag, __float_as_uint(p1.z), __float_as_uint(p1.w), __float_as_uint(p2.x));
    stcg_v4(base+3, tag, __float_as_uint(p2.y), __float_as_uint(p2.z), __float_as_uint(p2.w));
}

__global__ __launch_bounds__(T, 1) void pose_ode_kernel(
    const float* __restrict__ ts,
    const float* __restrict__ w1, const float* __restrict__ b1,
    const float* __restrict__ w2, const float* __restrict__ b2,
    const float* __restrict__ rw1, const float* __restrict__ rb1,
    const float* __restrict__ rw2, const float* __restrict__ rb2,
    const float* __restrict__ rw3, const float* __restrict__ rb3,
    const float* __restrict__ rw4, const float* __restrict__ rb4,
    float* __restrict__ out, int out_n)
{
    __shared__ float  wstage[NC * F];    // 36 KB one-time staging; regressor scratch
    __shared__ float4 vsm4[F / 4];       // stage input vector / final yT
    __shared__ float4 hsm4[F / 4];       // hidden vector / regressor scratch
    __shared__ float4 pack4[3];          // 12 packed outputs
    __shared__ float  red[8];
    __shared__ float  pose_s[8];
    __shared__ float  dts[NSTEP];

    float* vsm = (float*)vsm4;
    float* hsm = (float*)hsm4;
    float* pack_s = (float*)pack4;

    const int tid  = threadIdx.x;
    const int warp = tid >> 5;
    const int lane = tid & 31;
    const int half = (lane >> 4) & 1;    // lane0 -> col 2w, lane16 -> col 2w+1
    const int bid  = blockIdx.x;
    const int c0   = bid * NC;

    if (tid < NSTEP) dts[tid] = __ldg(&ts[tid + 1]) - __ldg(&ts[tid]);

    // ---- stage weight columns into SMEM (coalesced), then into registers ----
    float4 w1a[6], w1b[6], w2a[6], w2b[6];
    for (int idx = tid; idx < NC * F; idx += T) {
        int i = idx / NC, r = idx - i * NC;
        wstage[r * F + i] = w1[i * F + c0 + r];
    }
    __syncthreads();
#pragma unroll
    for (int k = 0; k < 6; k++) {
        w1a[k] = ((const float4*)(wstage + (2 * warp)     * F))[k * 32 + lane];
        w1b[k] = ((const float4*)(wstage + (2 * warp + 1) * F))[k * 32 + lane];
    }
    __syncthreads();
    for (int idx = tid; idx < NC * F; idx += T) {
        int i = idx / NC, r = idx - i * NC;
        wstage[r * F + i] = w2[i * F + c0 + r];
    }
    __syncthreads();
#pragma unroll
    for (int k = 0; k < 6; k++) {
        w2a[k] = ((const float4*)(wstage + (2 * warp)     * F))[k * 32 + lane];
        w2b[k] = ((const float4*)(wstage + (2 * warp + 1) * F))[k * 32 + lane];
    }

    // per-lane bias for this lane's writer column (lane0: 2w, lane16: 2w+1)
    const float b1c = __ldg(&b1[c0 + 2 * warp + half]);
    const float b2c = __ldg(&b2[c0 + 2 * warp + half]);

    // ---- initial state: y0 = 0 ----
    if (tid < F / 4) vsm4[tid] = make_float4(0.f, 0.f, 0.f, 0.f);
    __syncthreads();

    // Poller thread t (<64) owns state elements [12t, 12t+12) == its packet.
    float yr[12], ynr[12], k1r[12], k2r[12];
#pragma unroll
    for (int q = 0; q < 12; q++) yr[q] = 0.f;
    unsigned rnd = 0;

#pragma unroll 1
    for (int s = 0; s < NSTEP; s++) {
        const float dt  = dts[s];
        const float dt3 = dt * (1.0f / 3.0f);

#pragma unroll 1
        for (int e = 0; e < 4; e++) {
            // ---- layer 1: h = tanh(v @ W1 + b1), 2 columns per warp ----
            float acc = dot2(vsm4, w1a, w1b, lane, half);
            float hvv = tanhf(acc + b1c);
            if (lane == 0 || lane == 16) pack_s[2 * warp + half] = hvv;
            __syncthreads();                    // pack_s complete
            unsigned th = ++rnd;
            if (tid == 0) publish12(pack4, th, g_x[th & 1][bid]);
            if (tid < G) {
                float hv[12];
                wait_packet(g_x[th & 1][tid], th, hv);
                float4* d = (float4*)(hsm + tid * 12);
                d[0] = make_float4(hv[0], hv[1], hv[2],  hv[3]);
                d[1] = make_float4(hv[4], hv[5], hv[6],  hv[7]);
                d[2] = make_float4(hv[8], hv[9], hv[10], hv[11]);
            }
            __syncthreads();                    // hsm complete

            // ---- layer 2: k = h @ W2 + b2 ----
            float acc2 = dot2(hsm4, w2a, w2b, lane, half);
            float kvv = acc2 + b2c;
            if (lane == 0 || lane == 16) pack_s[2 * warp + half] = kvv;
            __syncthreads();                    // pack_s complete
            unsigned tk = ++rnd;
            if (tid == 0) publish12(pack4, tk, g_x[tk & 1][bid]);
            if (tid < G) {
                float kv[12], vv[12];
                wait_packet(g_x[tk & 1][tid], tk, kv);
                if (e == 0) {
#pragma unroll
                    for (int q = 0; q < 12; q++) {
                        k1r[q] = kv[q];
                        ynr[q] = fmaf(dt * 0.125f, kv[q], yr[q]);
                        vv[q]  = fmaf(dt3, kv[q], yr[q]);
                    }
                } else if (e == 1) {
#pragma unroll
                    for (int q = 0; q < 12; q++) {
                        k2r[q] = kv[q];
                        ynr[q] = fmaf(dt * 0.375f, kv[q], ynr[q]);
                        vv[q]  = yr[q] + dt * kv[q] - dt3 * k1r[q];
                    }
                } else if (e == 2) {
#pragma unroll
                    for (int q = 0; q < 12; q++) {
                        ynr[q] = fmaf(dt * 0.375f, kv[q], ynr[q]);
                        vv[q]  = yr[q] + dt * (k1r[q] - k2r[q] + kv[q]);
                    }
                } else {
#pragma unroll
                    for (int q = 0; q < 12; q++) {
                        yr[q] = fmaf(dt * 0.125f, kv[q], ynr[q]);
                        vv[q] = yr[q];
                    }
                }
                float4* v = (float4*)(vsm + tid * 12);
                v[0] = make_float4(vv[0], vv[1], vv[2],  vv[3]);
                v[1] = make_float4(vv[4], vv[5], vv[6],  vv[7]);
                v[2] = make_float4(vv[8], vv[9], vv[10], vv[11]);
            }
            __syncthreads();                    // vsm complete
        }
    }
    // vsm now holds yT (not modified below).

    // ---- regressor 768->128->256->128->6 via tagged 8B rounds ----
    float* scratch = wstage;   // weight staging no longer needed
    {
        float o1a = block_dot(vsm, 768, rw1, 128, bid,      rb1, red);
        float o1b = block_dot(vsm, 768, rw1, 128, bid + 64, rb1, red);
        unsigned tr = ++rnd; uint2* b = g_s[tr & 1];
        if (tid == 0) {
            pub8(&b[bid],      lrelu(o1a), tr);
            pub8(&b[bid + 64], lrelu(o1b), tr);
        }
        if (tid < 128) hsm[tid] = wait8(&b[tid], tr);
        __syncthreads();

        float o2[4];
#pragma unroll
        for (int m = 0; m < 4; m++)
            o2[m] = block_dot(hsm, 128, rw2, 256, bid + m * 64, rb2, red);
        tr = ++rnd; b = g_s[tr & 1];
        if (tid == 0)
#pragma unroll
            for (int m = 0; m < 4; m++) pub8(&b[bid + m * 64], lrelu(o2[m]), tr);
        for (int i = tid; i < 256; i += T) scratch[i] = wait8(&b[i], tr);
        __syncthreads();

        float o3a = block_dot(scratch, 256, rw3, 128, bid,      rb3, red);
        float o3b = block_dot(scratch, 256, rw3, 128, bid + 64, rb3, red);
        tr = ++rnd; b = g_s[tr & 1];
        if (tid == 0) {
            pub8(&b[bid],      lrelu(o3a), tr);
            pub8(&b[bid + 64], lrelu(o3b), tr);
        }
        __syncthreads();                 // hsm reads done above
        if (tid < 128) hsm[tid] = wait8(&b[tid], tr);
        __syncthreads();

        float o4 = block_dot(hsm, 128, rw4, 6, bid % 6, rb4, red);
        tr = ++rnd; b = g_s[tr & 1];
        if (tid == 0 && bid < 6) pub8(&b[bid], o4, tr);   // no activation
        if (tid < 6) pose_s[tid] = wait8(&b[tid], tr);
        __syncthreads();
    }

    // ---- outputs: [pose (256*6) | yT (256*768)] ----
    for (int idx = bid * T + tid; idx < out_n; idx += G * T) {
        out[idx] = (idx < 1536) ? pose_s[idx % 6] : vsm[(idx - 1536) % 768];
    }
}

extern "C" void kernel_launch(void* const* d_in, const int* in_sizes, int n_in,
                              void* d_out, int out_size) {
    // order: fv, fv_alter, fi, dec (unused), ts, ode_w1, ode_b1, ode_w2, ode_b2,
    // reg_w1, reg_b1, reg_w2, reg_b2, reg_w3, reg_b3, reg_w4, reg_b4
    const float* ts  = (const float*)d_in[4];
    const float* w1  = (const float*)d_in[5];
    const float* b1  = (const float*)d_in[6];
    const float* w2  = (const float*)d_in[7];
    const float* b2  = (const float*)d_in[8];
    const float* rw1 = (const float*)d_in[9];
    const float* rb1 = (const float*)d_in[10];
    const float* rw2 = (const float*)d_in[11];
    const float* rb2 = (const float*)d_in[12];
    const float* rw3 = (const float*)d_in[13];
    const float* rb3 = (const float*)d_in[14];
    const float* rw4 = (const float*)d_in[15];
    const float* rb4 = (const float*)d_in[16];

    pose_ode_kernel<<<G, T>>>(ts, w1, b1, w2, b2,
                              rw1, rb1, rw2, rb2, rw3, rb3, rw4, rb4,
                              (float*)d_out, out_size);
}